// round 1
// baseline (speedup 1.0000x reference)
#include <cuda_runtime.h>

typedef unsigned long long ULL;

// ---------- packed f32x2 helpers (Blackwell: fma.rn.f32x2 only via PTX) ----------
__device__ __forceinline__ ULL pk2(float a, float b) {
    ULL r; asm("mov.b64 %0, {%1, %2};" : "=l"(r) : "f"(a), "f"(b)); return r;
}
__device__ __forceinline__ void upk2(ULL v, float& a, float& b) {
    asm("mov.b64 {%0, %1}, %2;" : "=f"(a), "=f"(b) : "l"(v));
}
__device__ __forceinline__ ULL ffma2(ULL a, ULL b, ULL c) {
    ULL d; asm("fma.rn.f32x2 %0, %1, %2, %3;" : "=l"(d) : "l"(a), "l"(b), "l"(c)); return d;
}
__device__ __forceinline__ ULL fmul2(ULL a, ULL b) {
    ULL d; asm("mul.rn.f32x2 %0, %1, %2;" : "=l"(d) : "l"(a), "l"(b)); return d;
}

// ---------- problem constants ----------
constexpr int Bb = 4, Ls = 1024, Dd = 1280, Hh = 20, DHc = 64;
constexpr int Mrows = Bb * Ls;            // 4096
constexpr float ALPHA = 0.48f;
constexpr float SCALE = 0.125f;           // 1/sqrt(64)

// ---------- scratch (static __device__ arrays; no allocation allowed) ----------
__device__ float g_Q[Mrows * Dd];
__device__ float g_K[Mrows * Dd];
__device__ float g_V[Mrows * Dd];
__device__ float g_CTX[Mrows * Dd];

// =====================================================================
// SGEMM: C[M,N] = A[M,K] @ B[K,N] (+bias), M=4096, N=K=1280
// 128x128 block tile, TK=8, 256 threads, 8x8 microtile, f32x2 FMAs.
// blockIdx.z selects among (B0,C0),(B1,C1),(B2,C2) for fused QKV.
// =====================================================================
__global__ __launch_bounds__(256, 2)
void sgemm_kernel(const float* __restrict__ A,
                  const float* __restrict__ B0, const float* __restrict__ B1,
                  const float* __restrict__ B2,
                  float* __restrict__ C0, float* __restrict__ C1, float* __restrict__ C2,
                  const float* __restrict__ bias)
{
    const int z = blockIdx.z;
    const float* __restrict__ B = (z == 0) ? B0 : (z == 1) ? B1 : B2;
    float* __restrict__ C = (z == 0) ? C0 : (z == 1) ? C1 : C2;

    __shared__ float As[2][8][128];   // transposed: As[k][m]
    __shared__ float Bs[2][8][128];   // natural:   Bs[k][n]

    const int t = threadIdx.x;
    const int mblk = blockIdx.y * 128;
    const int nblk = blockIdx.x * 128;
    const int tx = t & 15, ty = t >> 4;
    const int m0 = ty * 8, n0 = tx * 8;

    ULL acc[8][4];
#pragma unroll
    for (int i = 0; i < 8; i++)
#pragma unroll
        for (int j = 0; j < 4; j++) acc[i][j] = 0ull;

    const int lm = t >> 1, lkq = (t & 1) * 4;   // A-tile load: row lm, k-quad lkq
    const int lkb = t >> 5, ln = (t & 31) * 4;  // B-tile load: k-row lkb, col quad ln
    const float* Aptr = A + (mblk + lm) * Dd + lkq;
    const float* Bptr = B + lkb * Dd + nblk + ln;

    // preload tile 0
    {
        float4 av = *(const float4*)Aptr;
        float4 bv = *(const float4*)Bptr;
        As[0][lkq + 0][lm] = av.x; As[0][lkq + 1][lm] = av.y;
        As[0][lkq + 2][lm] = av.z; As[0][lkq + 3][lm] = av.w;
        *(float4*)&Bs[0][lkb][ln] = bv;
    }
    __syncthreads();

    const int KT = Dd / 8;  // 160
    int cur = 0;
    for (int kt = 0; kt < KT; ++kt) {
        float4 an, bn;
        if (kt + 1 < KT) {
            an = *(const float4*)(Aptr + (kt + 1) * 8);
            bn = *(const float4*)(Bptr + (size_t)(kt + 1) * 8 * Dd);
        }
#pragma unroll
        for (int k = 0; k < 8; ++k) {
            float4 a0 = *(const float4*)&As[cur][k][m0];
            float4 a1 = *(const float4*)&As[cur][k][m0 + 4];
            float4 b0 = *(const float4*)&Bs[cur][k][n0];
            float4 b1 = *(const float4*)&Bs[cur][k][n0 + 4];
            ULL bq[4] = { pk2(b0.x, b0.y), pk2(b0.z, b0.w),
                          pk2(b1.x, b1.y), pk2(b1.z, b1.w) };
            ULL ap[8] = { pk2(a0.x, a0.x), pk2(a0.y, a0.y), pk2(a0.z, a0.z), pk2(a0.w, a0.w),
                          pk2(a1.x, a1.x), pk2(a1.y, a1.y), pk2(a1.z, a1.z), pk2(a1.w, a1.w) };
#pragma unroll
            for (int i = 0; i < 8; i++)
#pragma unroll
                for (int j = 0; j < 4; j++)
                    acc[i][j] = ffma2(ap[i], bq[j], acc[i][j]);
        }
        if (kt + 1 < KT) {
            const int nxt = cur ^ 1;
            As[nxt][lkq + 0][lm] = an.x; As[nxt][lkq + 1][lm] = an.y;
            As[nxt][lkq + 2][lm] = an.z; As[nxt][lkq + 3][lm] = an.w;
            *(float4*)&Bs[nxt][lkb][ln] = bn;
        }
        __syncthreads();
        cur ^= 1;
    }

#pragma unroll
    for (int i = 0; i < 8; i++) {
        float o[8];
#pragma unroll
        for (int j = 0; j < 4; j++) upk2(acc[i][j], o[2 * j], o[2 * j + 1]);
        if (bias) {
#pragma unroll
            for (int c = 0; c < 8; c++) o[c] += bias[nblk + n0 + c];
        }
        float* Crow = C + (size_t)(mblk + m0 + i) * Dd + nblk + n0;
        *(float4*)Crow       = make_float4(o[0], o[1], o[2], o[3]);
        *(float4*)(Crow + 4) = make_float4(o[4], o[5], o[6], o[7]);
    }
}

// =====================================================================
// Flash attention: per block = (q-tile of 128 rows) x (one head bh).
// KV length 2048 = 1024 computed K/V + 1024 background (scaled by ALPHA).
// 256 threads; microtile 8 q-rows (4 f32x2 pairs) x 4 cols; online softmax.
// Smem: Qst[d][r] 64x128, Kst[d][c] 64x64, Vs[c][d] 64x64, Sst[c][r] 64x128.
// =====================================================================
__global__ __launch_bounds__(256)
void attn_kernel(const float* __restrict__ Kbg, const float* __restrict__ Vbg)
{
    extern __shared__ float sm[];
    float* Qst = sm;                       // 64*128
    float* Kst = Qst + 64 * 128;           // 64*64
    float* Vs  = Kst + 64 * 64;            // 64*64
    float* Sst = Vs  + 64 * 64;            // 64*128
    float* m_s = Sst + 64 * 128;           // 128
    float* l_s = m_s + 128;                // 128
    float* cf_s = l_s + 128;               // 128

    const int t = threadIdx.x;
    const int qblk = blockIdx.x * 128;
    const int bh = blockIdx.y;             // 0..79
    const int b = bh / Hh;
    const int h = bh % Hh;

    const int tx = t & 15, ty = t >> 4;
    const int r0 = ty * 8;                 // 8 q-rows per thread
    const int c0 = tx * 4;                 // 4 cols (keys in S-GEMM, dims in PV)

    // ---- load Q tile transposed: Qst[d][r] ----
    {
        const int r = t >> 1;
        const int dq = (t & 1) * 32;
        const float* qrow = g_Q + (size_t)(b * Ls + qblk + r) * Dd + h * DHc + dq;
#pragma unroll
        for (int u = 0; u < 8; ++u) {
            float4 v = *(const float4*)(qrow + 4 * u);
            Qst[(dq + 4 * u + 0) * 128 + r] = v.x;
            Qst[(dq + 4 * u + 1) * 128 + r] = v.y;
            Qst[(dq + 4 * u + 2) * 128 + r] = v.z;
            Qst[(dq + 4 * u + 3) * 128 + r] = v.w;
        }
    }
    if (t < 128) { m_s[t] = -1e30f; l_s[t] = 0.f; }

    ULL oacc[4][4];
#pragma unroll
    for (int p = 0; p < 4; p++)
#pragma unroll
        for (int j = 0; j < 4; j++) oacc[p][j] = 0ull;

    for (int jt = 0; jt < 32; ++jt) {
        __syncthreads();   // prev PV done (and, first iter, Q/m/l init done)

        // ---- load K (transposed) and V tiles, folding ALPHA for bg half ----
        {
            const int c = t >> 2;
            const int dq = (t & 3) * 16;
            const int kg = jt * 64 + c;
            const float* ksrc; const float* vsrc; float amul;
            if (kg < Ls) {
                ksrc = g_K + (size_t)(b * Ls + kg) * Dd + h * DHc + dq;
                vsrc = g_V + (size_t)(b * Ls + kg) * Dd + h * DHc + dq;
                amul = 1.f;
            } else {
                ksrc = Kbg + (size_t)(bh * Ls + (kg - Ls)) * DHc + dq;
                vsrc = Vbg + (size_t)(bh * Ls + (kg - Ls)) * DHc + dq;
                amul = ALPHA;
            }
#pragma unroll
            for (int u = 0; u < 4; ++u) {
                float4 kv = *(const float4*)(ksrc + 4 * u);
                Kst[(dq + 4 * u + 0) * 64 + c] = amul * kv.x;
                Kst[(dq + 4 * u + 1) * 64 + c] = amul * kv.y;
                Kst[(dq + 4 * u + 2) * 64 + c] = amul * kv.z;
                Kst[(dq + 4 * u + 3) * 64 + c] = amul * kv.w;
                float4 vv = *(const float4*)(vsrc + 4 * u);
                vv.x *= amul; vv.y *= amul; vv.z *= amul; vv.w *= amul;
                *(float4*)&Vs[c * 64 + dq + 4 * u] = vv;
            }
        }
        __syncthreads();

        // ---- S = (Q K^T) * SCALE, row-paired f32x2 ----
        ULL sacc[4][4];
#pragma unroll
        for (int p = 0; p < 4; p++)
#pragma unroll
            for (int j = 0; j < 4; j++) sacc[p][j] = 0ull;

#pragma unroll 4
        for (int d = 0; d < 64; ++d) {
            ULL qp[4];
#pragma unroll
            for (int p = 0; p < 4; p++) qp[p] = *(const ULL*)&Qst[d * 128 + r0 + 2 * p];
            float4 kv = *(const float4*)&Kst[d * 64 + c0];
            ULL kk[4] = { pk2(kv.x, kv.x), pk2(kv.y, kv.y), pk2(kv.z, kv.z), pk2(kv.w, kv.w) };
#pragma unroll
            for (int p = 0; p < 4; p++)
#pragma unroll
                for (int j = 0; j < 4; j++)
                    sacc[p][j] = ffma2(qp[p], kk[j], sacc[p][j]);
        }
        // store S transposed: Sst[c][r]
#pragma unroll
        for (int p = 0; p < 4; p++)
#pragma unroll
            for (int j = 0; j < 4; j++) {
                float s0, s1; upk2(sacc[p][j], s0, s1);
                *(ULL*)&Sst[(c0 + j) * 128 + r0 + 2 * p] = pk2(s0 * SCALE, s1 * SCALE);
            }
        __syncthreads();

        // ---- online softmax over this 64-key tile (2 threads per q-row) ----
        {
            const int r = t >> 1;
            const int cb = (t & 1) * 32;
            float mx = -1e30f;
#pragma unroll
            for (int i = 0; i < 32; ++i) mx = fmaxf(mx, Sst[(cb + i) * 128 + r]);
            mx = fmaxf(mx, __shfl_xor_sync(0xffffffffu, mx, 1));
            const float m_old = m_s[r];
            const float m_new = fmaxf(m_old, mx);
            float sum = 0.f;
#pragma unroll
            for (int i = 0; i < 32; ++i) {
                float p = __expf(Sst[(cb + i) * 128 + r] - m_new);
                Sst[(cb + i) * 128 + r] = p;
                sum += p;
            }
            sum += __shfl_xor_sync(0xffffffffu, sum, 1);
            if ((t & 1) == 0) {
                const float cf = __expf(m_old - m_new);
                cf_s[r] = cf;
                l_s[r] = l_s[r] * cf + sum;
                m_s[r] = m_new;
            }
        }
        __syncthreads();

        // ---- O = O*cf + P V, row-paired f32x2 ----
        {
#pragma unroll
            for (int p = 0; p < 4; p++) {
                ULL cfp = *(const ULL*)&cf_s[r0 + 2 * p];
#pragma unroll
                for (int j = 0; j < 4; j++) oacc[p][j] = fmul2(oacc[p][j], cfp);
            }
#pragma unroll 4
            for (int c = 0; c < 64; ++c) {
                ULL pp[4];
#pragma unroll
                for (int p = 0; p < 4; p++) pp[p] = *(const ULL*)&Sst[c * 128 + r0 + 2 * p];
                float4 v4 = *(const float4*)&Vs[c * 64 + c0];
                ULL vv[4] = { pk2(v4.x, v4.x), pk2(v4.y, v4.y), pk2(v4.z, v4.z), pk2(v4.w, v4.w) };
#pragma unroll
                for (int p = 0; p < 4; p++)
#pragma unroll
                    for (int j = 0; j < 4; j++)
                        oacc[p][j] = ffma2(pp[p], vv[j], oacc[p][j]);
            }
        }
    }

    // ---- epilogue: divide by l, scatter to g_CTX in [B,L,D] head-interleaved ----
#pragma unroll
    for (int p = 0; p < 4; p++) {
        const float la = l_s[r0 + 2 * p];
        const float lb = l_s[r0 + 2 * p + 1];
        const float ra = 1.f / la, rb = 1.f / lb;
        float o0[4], o1[4];
#pragma unroll
        for (int j = 0; j < 4; j++) {
            float x, y; upk2(oacc[p][j], x, y);
            o0[j] = x * ra; o1[j] = y * rb;
        }
        const size_t base = (size_t)(b * Ls + qblk + r0 + 2 * p) * Dd + h * DHc + c0;
        *(float4*)&g_CTX[base]      = make_float4(o0[0], o0[1], o0[2], o0[3]);
        *(float4*)&g_CTX[base + Dd] = make_float4(o1[0], o1[1], o1[2], o1[3]);
    }
}

// =====================================================================
// launch
// =====================================================================
extern "C" void kernel_launch(void* const* d_in, const int* in_sizes, int n_in,
                              void* d_out, int out_size)
{
    const float* X   = (const float*)d_in[0];
    const float* Wq  = (const float*)d_in[1];
    const float* Wk  = (const float*)d_in[2];
    const float* Wv  = (const float*)d_in[3];
    const float* Wo  = (const float*)d_in[4];
    const float* bo  = (const float*)d_in[5];
    const float* Kbg = (const float*)d_in[6];
    const float* Vbg = (const float*)d_in[7];
    float* out = (float*)d_out;

    float *Q, *K, *V, *CTX;
    cudaGetSymbolAddress((void**)&Q,   g_Q);
    cudaGetSymbolAddress((void**)&K,   g_K);
    cudaGetSymbolAddress((void**)&V,   g_V);
    cudaGetSymbolAddress((void**)&CTX, g_CTX);

    // 1) fused QKV projections
    dim3 g1(Dd / 128, Mrows / 128, 3);
    sgemm_kernel<<<g1, 256>>>(X, Wq, Wk, Wv, Q, K, V, nullptr);

    // 2) attention with injected background K/V
    const int smem_bytes = (64 * 128 + 64 * 64 + 64 * 64 + 64 * 128 + 3 * 128) * 4; // 99840
    cudaFuncSetAttribute(attn_kernel, cudaFuncAttributeMaxDynamicSharedMemorySize, smem_bytes);
    dim3 g2(Ls / 128, Bb * Hh);
    attn_kernel<<<g2, 256, smem_bytes>>>(Kbg, Vbg);

    // 3) output projection (+bias)
    dim3 g3(Dd / 128, Mrows / 128, 1);
    sgemm_kernel<<<g3, 256>>>(CTX, Wo, Wo, Wo, out, out, out, bo);
}

// round 3
// speedup vs baseline: 2.2950x; 2.2950x over previous
#include <cuda_runtime.h>
#include <cstdint>

// ---------------- problem constants ----------------
constexpr int Bb = 4, Ls = 1024, Dd = 1280, Hh = 20, DHc = 64;
constexpr int Mrows = Bb * Ls;            // 4096
constexpr float ALPHA = 0.48f;
constexpr float SCALE = 0.125f;           // 1/sqrt(64)
constexpr int NK = Dd * Dd;

// ---------------- device scratch ----------------
__device__ float g_Q[Mrows * Dd];
__device__ float g_K[Mrows * Dd];
__device__ float g_V[Mrows * Dd];
__device__ float g_CTX[Mrows * Dd];
__device__ float g_Wt[4 * NK];      // transposed + tf32-rounded weights (q,k,v,o)
__device__ float g_Xt[Mrows * Dd];  // tf32-rounded X

// ---------------- helpers ----------------
__device__ __forceinline__ uint32_t smem_u32(const void* p) {
    uint32_t a;
    asm("{ .reg .u64 t; cvta.to.shared.u64 t, %1; cvt.u32.u64 %0, t; }" : "=r"(a) : "l"(p));
    return a;
}
__device__ __forceinline__ float rna_tf32(float x) {
    float r; asm("cvt.rna.tf32.f32 %0, %1;" : "=f"(r) : "f"(x)); return r;
}
// m16n8k8 tf32 mma: D += A*B, A row-major 16x8 (4 regs), B col-major 8x8 (2 regs)
__device__ __forceinline__ void mma8(float* d, uint32_t a0, uint32_t a1, uint32_t a2, uint32_t a3,
                                     uint32_t b0, uint32_t b1) {
    asm volatile("mma.sync.aligned.m16n8k8.row.col.f32.tf32.tf32.f32 "
                 "{%0,%1,%2,%3}, {%4,%5,%6,%7}, {%8,%9}, {%0,%1,%2,%3};"
                 : "+f"(d[0]), "+f"(d[1]), "+f"(d[2]), "+f"(d[3])
                 : "r"(a0), "r"(a1), "r"(a2), "r"(a3), "r"(b0), "r"(b1));
}
// swizzled float-index into tiles with 32-col / 64-col row stride
__device__ __forceinline__ int swz32i(int r, int c) { return r * 32 + (c ^ ((r & 7) << 2)); }
__device__ __forceinline__ int swz64i(int r, int c) { return r * 64 + (c ^ ((r & 7) << 2)); }
__device__ __forceinline__ uint32_t f2u(float x) { return __float_as_uint(x); }

// =====================================================================
// pre-pass 1: round X to tf32 grid
// =====================================================================
__global__ void round_x_kernel(const float* __restrict__ in, float* __restrict__ out) {
    int i = blockIdx.x * blockDim.x + threadIdx.x;   // float4 index
    float4 v = ((const float4*)in)[i];
    v.x = rna_tf32(v.x); v.y = rna_tf32(v.y);
    v.z = rna_tf32(v.z); v.w = rna_tf32(v.w);
    ((float4*)out)[i] = v;
}

// =====================================================================
// pre-pass 2: transpose weights [K,N] -> [N,K] with tf32 rounding
// =====================================================================
__global__ void transpose_w_kernel(const float* __restrict__ W0, const float* __restrict__ W1,
                                   const float* __restrict__ W2, const float* __restrict__ W3,
                                   float* __restrict__ out) {
    __shared__ float s[32][33];
    const int z = blockIdx.z;
    const float* W = (z == 0) ? W0 : (z == 1) ? W1 : (z == 2) ? W2 : W3;
    float* O = out + (size_t)z * NK;
    const int bx = blockIdx.x * 32, by = blockIdx.y * 32;
    const int tx = threadIdx.x, ty = threadIdx.y;   // 32 x 8
#pragma unroll
    for (int i = 0; i < 4; i++)
        s[ty + 8 * i][tx] = W[(size_t)(by + ty + 8 * i) * Dd + bx + tx];
    __syncthreads();
#pragma unroll
    for (int i = 0; i < 4; i++)
        O[(size_t)(bx + ty + 8 * i) * Dd + by + tx] = rna_tf32(s[tx][ty + 8 * i]);
}

// =====================================================================
// tf32 mma.sync GEMM: C[M,N] = A[M,K] @ Wt[N,K]^T (+bias)
// 128x128 CTA tile, 8 warps (2m x 4n), warp tile 64x32, K chunk 32,
// 3-stage cp.async pipeline, swizzled smem, blockIdx.z selects (Wt,C).
// =====================================================================
constexpr int GK_STAGE_F = 8192;                 // floats per stage (A 4096 + B 4096)
constexpr int GK_SMEM = 3 * 32768 + 1024;

__device__ __forceinline__ void gk_load_chunk(const float* __restrict__ A,
                                              const float* __restrict__ Wt,
                                              int mblk, int nblk, int kc,
                                              uint32_t aB, uint32_t bB, int t) {
#pragma unroll
    for (int u = 0; u < 4; u++) {
        const int seg = u * 256 + t;
        const int row = seg >> 3, q = seg & 7;
        const float* srcA = A + (size_t)(mblk + row) * Dd + kc + q * 4;
        uint32_t da = aB + (uint32_t)(row * 128 + ((q * 16) ^ ((row & 7) << 4)));
        asm volatile("cp.async.cg.shared.global [%0], [%1], 16;" :: "r"(da), "l"(srcA) : "memory");
        const float* srcB = Wt + (size_t)(nblk + row) * Dd + kc + q * 4;
        uint32_t db = bB + (uint32_t)(row * 128 + ((q * 16) ^ ((row & 7) << 4)));
        asm volatile("cp.async.cg.shared.global [%0], [%1], 16;" :: "r"(db), "l"(srcB) : "memory");
    }
    asm volatile("cp.async.commit_group;" ::: "memory");
}

__global__ __launch_bounds__(256, 1)
void gemm_mma_kernel(const float* __restrict__ A,
                     const float* __restrict__ Wt0, const float* __restrict__ Wt1,
                     const float* __restrict__ Wt2,
                     float* __restrict__ C0, float* __restrict__ C1, float* __restrict__ C2,
                     const float* __restrict__ bias)
{
    const int z = blockIdx.z;
    const float* __restrict__ Wt = (z == 0) ? Wt0 : (z == 1) ? Wt1 : Wt2;
    float* __restrict__ C = (z == 0) ? C0 : (z == 1) ? C1 : C2;
    const int mblk = blockIdx.y * 128, nblk = blockIdx.x * 128;
    const int t = threadIdx.x, w = t >> 5, lane = t & 31;

    extern __shared__ float dysm[];
    const uint32_t raw = smem_u32(dysm);
    const uint32_t sbu = (raw + 1023u) & ~1023u;
    float* sb = dysm + ((sbu - raw) >> 2);

    float acc[4][4][4];
#pragma unroll
    for (int i = 0; i < 4; i++)
#pragma unroll
        for (int j = 0; j < 4; j++)
#pragma unroll
            for (int k = 0; k < 4; k++) acc[i][j][k] = 0.f;

    const int nch = Dd / 32;  // 40
    const int wm = (w & 1) * 64, wn = (w >> 1) * 32;
    const int lq = lane >> 2, lr = lane & 3;

    // prologue: fill 3 stages
#pragma unroll
    for (int c = 0; c < 3; c++)
        gk_load_chunk(A, Wt, mblk, nblk, c * 32, sbu + c * 32768, sbu + c * 32768 + 16384, t);

#pragma unroll 1
    for (int i = 0; i < nch; i++) {
        const int s = i - (i / 3) * 3;
        if (i <= nch - 3)      asm volatile("cp.async.wait_group 2;" ::: "memory");
        else if (i == nch - 2) asm volatile("cp.async.wait_group 1;" ::: "memory");
        else                   asm volatile("cp.async.wait_group 0;" ::: "memory");
        __syncthreads();

        const float* As = sb + s * GK_STAGE_F;
        const float* Bs = As + 4096;
#pragma unroll
        for (int ks = 0; ks < 4; ks++) {
            const int c = ks * 8 + lr;
            uint32_t af[4][4];
#pragma unroll
            for (int f = 0; f < 4; f++) {
                const int r = wm + 16 * f + lq;
                af[f][0] = f2u(As[swz32i(r, c)]);
                af[f][1] = f2u(As[swz32i(r + 8, c)]);
                af[f][2] = f2u(As[swz32i(r, c + 4)]);
                af[f][3] = f2u(As[swz32i(r + 8, c + 4)]);
            }
#pragma unroll
            for (int fn = 0; fn < 4; fn++) {
                const int n = wn + 8 * fn + lq;
                const uint32_t b0 = f2u(Bs[swz32i(n, c)]);
                const uint32_t b1 = f2u(Bs[swz32i(n, c + 4)]);
#pragma unroll
                for (int f = 0; f < 4; f++)
                    mma8(acc[f][fn], af[f][0], af[f][1], af[f][2], af[f][3], b0, b1);
            }
        }

        if (i + 3 < nch) {
            __syncthreads();
            gk_load_chunk(A, Wt, mblk, nblk, (i + 3) * 32,
                          sbu + s * 32768, sbu + s * 32768 + 16384, t);
        }
    }

    // epilogue
#pragma unroll
    for (int f = 0; f < 4; f++) {
#pragma unroll
        for (int fn = 0; fn < 4; fn++) {
            const int r = mblk + wm + 16 * f + lq;
            const int cc = nblk + wn + 8 * fn + 2 * lr;
            float v0 = acc[f][fn][0], v1 = acc[f][fn][1];
            float v2 = acc[f][fn][2], v3 = acc[f][fn][3];
            if (bias) {
                const float b0 = bias[cc], b1 = bias[cc + 1];
                v0 += b0; v1 += b1; v2 += b0; v3 += b1;
            }
            *(float2*)&C[(size_t)r * Dd + cc]       = make_float2(v0, v1);
            *(float2*)&C[(size_t)(r + 8) * Dd + cc] = make_float2(v2, v3);
        }
    }
}

// =====================================================================
// Flash attention with tf32 mma.sync.
// CTA = 128 q-rows x one head; kv loop 2048 in 64-key tiles.
// 8 warps: warp w owns q-rows [w*16, w*16+16), all 64 cols.
// Qs[128][64] (Q*SCALE, tf32), Ks[64][64] key-major, Vt[64][64] d-major,
// Ss[128][64] scores/probs; all XOR-swizzled.
// =====================================================================
constexpr int ATT_SMEM = (8192 + 4096 + 4096 + 8192 + 384) * 4 + 1024;

__global__ __launch_bounds__(256)
void attn_kernel(const float* __restrict__ Kbg, const float* __restrict__ Vbg)
{
    extern __shared__ float dysm[];
    const uint32_t raw = smem_u32(dysm);
    const uint32_t sbu = (raw + 1023u) & ~1023u;
    float* base = dysm + ((sbu - raw) >> 2);

    float* Qs  = base;             // 128*64
    float* Ks  = Qs + 8192;        // 64*64
    float* Vt  = Ks + 4096;        // 64*64
    float* Ss  = Vt + 4096;        // 128*64
    float* m_s = Ss + 8192;        // 128
    float* l_s = m_s + 128;        // 128
    float* cf_s = l_s + 128;       // 128

    const int t = threadIdx.x, w = t >> 5, lane = t & 31;
    const int qblk = blockIdx.x * 128;
    const int bh = blockIdx.y;
    const int b = bh / Hh, h = bh % Hh;
    const int lq = lane >> 2, lr = lane & 3;
    const int rA = w * 16 + lq;          // this thread's low q-row

    // ---- load Q tile: scale + tf32 round, swizzled row-major ----
    {
        const int r = t >> 1;
        const int dq = (t & 1) * 32;
        const float* qrow = g_Q + (size_t)(b * Ls + qblk + r) * Dd + h * DHc + dq;
#pragma unroll
        for (int u = 0; u < 8; ++u) {
            float4 v = *(const float4*)(qrow + 4 * u);
            v.x = rna_tf32(v.x * SCALE); v.y = rna_tf32(v.y * SCALE);
            v.z = rna_tf32(v.z * SCALE); v.w = rna_tf32(v.w * SCALE);
            *(float4*)&Qs[swz64i(r, dq + 4 * u)] = v;
        }
    }
    if (t < 128) { m_s[t] = -1e30f; l_s[t] = 0.f; }

    float acc[8][4];
#pragma unroll
    for (int fn = 0; fn < 8; fn++)
#pragma unroll
        for (int j = 0; j < 4; j++) acc[fn][j] = 0.f;

    for (int jt = 0; jt < 32; ++jt) {
        __syncthreads();   // prev PV done; first iter: Q/m/l ready... (K/V reuse safe)

        // ---- load K (key-major) and V (transposed, d-major), alpha + tf32 ----
        {
            const int c = t >> 2;               // key 0..63
            const int dq = (t & 3) * 16;        // d-quad base
            const int kg = jt * 64 + c;
            const float* ksrc; const float* vsrc; float amul;
            if (kg < Ls) {
                ksrc = g_K + (size_t)(b * Ls + kg) * Dd + h * DHc + dq;
                vsrc = g_V + (size_t)(b * Ls + kg) * Dd + h * DHc + dq;
                amul = 1.f;
            } else {
                ksrc = Kbg + (size_t)(bh * Ls + (kg - Ls)) * DHc + dq;
                vsrc = Vbg + (size_t)(bh * Ls + (kg - Ls)) * DHc + dq;
                amul = ALPHA;
            }
#pragma unroll
            for (int u = 0; u < 4; ++u) {
                float4 kv = *(const float4*)(ksrc + 4 * u);
                kv.x = rna_tf32(kv.x * amul); kv.y = rna_tf32(kv.y * amul);
                kv.z = rna_tf32(kv.z * amul); kv.w = rna_tf32(kv.w * amul);
                *(float4*)&Ks[swz64i(c, dq + 4 * u)] = kv;
                float4 vv = *(const float4*)(vsrc + 4 * u);
                Vt[swz64i(dq + 4 * u + 0, c)] = rna_tf32(vv.x * amul);
                Vt[swz64i(dq + 4 * u + 1, c)] = rna_tf32(vv.y * amul);
                Vt[swz64i(dq + 4 * u + 2, c)] = rna_tf32(vv.z * amul);
                Vt[swz64i(dq + 4 * u + 3, c)] = rna_tf32(vv.w * amul);
            }
        }
        __syncthreads();

        // ---- S = Q K^T via mma ----
        float sacc[8][4];
#pragma unroll
        for (int fn = 0; fn < 8; fn++)
#pragma unroll
            for (int j = 0; j < 4; j++) sacc[fn][j] = 0.f;

#pragma unroll
        for (int kk = 0; kk < 8; kk++) {
            const int c = kk * 8 + lr;
            const uint32_t a0 = f2u(Qs[swz64i(rA, c)]);
            const uint32_t a1 = f2u(Qs[swz64i(rA + 8, c)]);
            const uint32_t a2 = f2u(Qs[swz64i(rA, c + 4)]);
            const uint32_t a3 = f2u(Qs[swz64i(rA + 8, c + 4)]);
#pragma unroll
            for (int fn = 0; fn < 8; fn++) {
                const int key = fn * 8 + lq;
                const uint32_t b0 = f2u(Ks[swz64i(key, c)]);
                const uint32_t b1 = f2u(Ks[swz64i(key, c + 4)]);
                mma8(sacc[fn], a0, a1, a2, a3, b0, b1);
            }
        }
        // write S to smem (fp32)
#pragma unroll
        for (int fn = 0; fn < 8; fn++) {
            const int col = fn * 8 + 2 * lr;
            *(float2*)&Ss[swz64i(rA, col)]     = make_float2(sacc[fn][0], sacc[fn][1]);
            *(float2*)&Ss[swz64i(rA + 8, col)] = make_float2(sacc[fn][2], sacc[fn][3]);
        }
        __syncthreads();

        // ---- online softmax over the 64-key tile (2 threads per q-row) ----
        {
            const int r = t >> 1;
            const int cb = (t & 1) * 32;
            float mx = -1e30f;
#pragma unroll
            for (int i = 0; i < 32; ++i) mx = fmaxf(mx, Ss[swz64i(r, cb + i)]);
            mx = fmaxf(mx, __shfl_xor_sync(0xffffffffu, mx, 1));
            const float m_old = m_s[r];
            const float m_new = fmaxf(m_old, mx);
            float sum = 0.f;
#pragma unroll
            for (int i = 0; i < 32; ++i) {
                const int idx = swz64i(r, cb + i);
                float p = __expf(Ss[idx] - m_new);
                Ss[idx] = rna_tf32(p);   // P pre-rounded for mma
                sum += p;
            }
            sum += __shfl_xor_sync(0xffffffffu, sum, 1);
            if ((t & 1) == 0) {
                const float cf = __expf(m_old - m_new);
                cf_s[r] = cf;
                l_s[r] = l_s[r] * cf + sum;
                m_s[r] = m_new;
            }
        }
        __syncthreads();

        // ---- O = O*cf + P V via mma ----
        const float cf_lo = cf_s[rA], cf_hi = cf_s[rA + 8];
#pragma unroll
        for (int fn = 0; fn < 8; fn++) {
            acc[fn][0] *= cf_lo; acc[fn][1] *= cf_lo;
            acc[fn][2] *= cf_hi; acc[fn][3] *= cf_hi;
        }
#pragma unroll
        for (int kk = 0; kk < 8; kk++) {
            const int c = kk * 8 + lr;       // key index within tile
            const uint32_t a0 = f2u(Ss[swz64i(rA, c)]);
            const uint32_t a1 = f2u(Ss[swz64i(rA + 8, c)]);
            const uint32_t a2 = f2u(Ss[swz64i(rA, c + 4)]);
            const uint32_t a3 = f2u(Ss[swz64i(rA + 8, c + 4)]);
#pragma unroll
            for (int fn = 0; fn < 8; fn++) {
                const int d = fn * 8 + lq;
                const uint32_t b0 = f2u(Vt[swz64i(d, c)]);
                const uint32_t b1 = f2u(Vt[swz64i(d, c + 4)]);
                mma8(acc[fn], a0, a1, a2, a3, b0, b1);
            }
        }
    }

    // ---- epilogue: /l, tf32-round (input to O-proj), scatter ----
    const float linv_lo = 1.f / l_s[rA];
    const float linv_hi = 1.f / l_s[rA + 8];
    const size_t row_lo = (size_t)(b * Ls + qblk + rA) * Dd + h * DHc;
    const size_t row_hi = (size_t)(b * Ls + qblk + rA + 8) * Dd + h * DHc;
#pragma unroll
    for (int fn = 0; fn < 8; fn++) {
        const int col = fn * 8 + 2 * lr;
        *(float2*)&g_CTX[row_lo + col] =
            make_float2(rna_tf32(acc[fn][0] * linv_lo), rna_tf32(acc[fn][1] * linv_lo));
        *(float2*)&g_CTX[row_hi + col] =
            make_float2(rna_tf32(acc[fn][2] * linv_hi), rna_tf32(acc[fn][3] * linv_hi));
    }
}

// =====================================================================
// launch
// =====================================================================
extern "C" void kernel_launch(void* const* d_in, const int* in_sizes, int n_in,
                              void* d_out, int out_size)
{
    const float* X   = (const float*)d_in[0];
    const float* Wq  = (const float*)d_in[1];
    const float* Wk  = (const float*)d_in[2];
    const float* Wv  = (const float*)d_in[3];
    const float* Wo  = (const float*)d_in[4];
    const float* bo  = (const float*)d_in[5];
    const float* Kbg = (const float*)d_in[6];
    const float* Vbg = (const float*)d_in[7];
    float* out = (float*)d_out;

    float *Q, *K, *V, *CTX, *Wt, *Xt;
    cudaGetSymbolAddress((void**)&Q,   g_Q);
    cudaGetSymbolAddress((void**)&K,   g_K);
    cudaGetSymbolAddress((void**)&V,   g_V);
    cudaGetSymbolAddress((void**)&CTX, g_CTX);
    cudaGetSymbolAddress((void**)&Wt,  g_Wt);
    cudaGetSymbolAddress((void**)&Xt,  g_Xt);

    // pre-passes
    round_x_kernel<<<Mrows * Dd / (256 * 4), 256>>>(X, Xt);
    transpose_w_kernel<<<dim3(Dd / 32, Dd / 32, 4), dim3(32, 8)>>>(Wq, Wk, Wv, Wo, Wt);

    // 1) fused QKV projections
    cudaFuncSetAttribute(gemm_mma_kernel, cudaFuncAttributeMaxDynamicSharedMemorySize, GK_SMEM);
    dim3 g1(Dd / 128, Mrows / 128, 3);
    gemm_mma_kernel<<<g1, 256, GK_SMEM>>>(Xt, Wt, Wt + NK, Wt + 2 * NK, Q, K, V, nullptr);

    // 2) attention with injected background K/V
    cudaFuncSetAttribute(attn_kernel, cudaFuncAttributeMaxDynamicSharedMemorySize, ATT_SMEM);
    dim3 g2(Ls / 128, Bb * Hh);
    attn_kernel<<<g2, 256, ATT_SMEM>>>(Kbg, Vbg);

    // 3) output projection (+bias)
    dim3 g3(Dd / 128, Mrows / 128, 1);
    gemm_mma_kernel<<<g3, 256, GK_SMEM>>>(CTX, Wt + 3 * NK, Wt + 3 * NK, Wt + 3 * NK,
                                          out, out, out, bo);
}

// round 4
// speedup vs baseline: 3.7418x; 1.6304x over previous
#include <cuda_runtime.h>
#include <cstdint>

// ---------------- problem constants ----------------
constexpr int Bb = 4, Ls = 1024, Dd = 1280, Hh = 20, DHc = 64;
constexpr int Mrows = Bb * Ls;            // 4096
constexpr float ALPHA = 0.48f;
constexpr float SCALE = 0.125f;           // 1/sqrt(64)
constexpr int NK = Dd * Dd;
constexpr int BH = Bb * Hh;               // 80
constexpr int KV = 2 * Ls;                // 2048

// ---------------- device scratch ----------------
__device__ float g_CTX[Mrows * Dd];
__device__ float g_Wt[4 * NK];            // transposed + tf32-rounded weights
__device__ float g_Xt[Mrows * Dd];        // tf32-rounded X
__device__ float g_Qh[BH * Ls * DHc];     // Q*SCALE, tf32, [bh][q][d]
__device__ float g_Kh[BH * KV * DHc];     // K (fg + alpha*bg), tf32, [bh][key][d]
__device__ float g_Vt[BH * DHc * KV];     // V transposed, tf32, [bh][d][key]

// ---------------- helpers ----------------
__device__ __forceinline__ uint32_t smem_u32(const void* p) {
    uint32_t a;
    asm("{ .reg .u64 t; cvta.to.shared.u64 t, %1; cvt.u32.u64 %0, t; }" : "=r"(a) : "l"(p));
    return a;
}
__device__ __forceinline__ float rna_tf32(float x) {
    float r; asm("cvt.rna.tf32.f32 %0, %1;" : "=f"(r) : "f"(x)); return r;
}
__device__ __forceinline__ void mma8(float* d, const uint32_t* a, uint32_t b0, uint32_t b1) {
    asm volatile("mma.sync.aligned.m16n8k8.row.col.f32.tf32.tf32.f32 "
                 "{%0,%1,%2,%3}, {%4,%5,%6,%7}, {%8,%9}, {%0,%1,%2,%3};"
                 : "+f"(d[0]), "+f"(d[1]), "+f"(d[2]), "+f"(d[3])
                 : "r"(a[0]), "r"(a[1]), "r"(a[2]), "r"(a[3]), "r"(b0), "r"(b1));
}
__device__ __forceinline__ void ldsm4(uint32_t* r, uint32_t addr) {
    asm volatile("ldmatrix.sync.aligned.m8n8.x4.shared.b16 {%0,%1,%2,%3}, [%4];"
                 : "=r"(r[0]), "=r"(r[1]), "=r"(r[2]), "=r"(r[3]) : "r"(addr));
}
__device__ __forceinline__ void cpasync16(uint32_t dst, const void* src) {
    asm volatile("cp.async.cg.shared.global [%0], [%1], 16;" :: "r"(dst), "l"(src) : "memory");
}
__device__ __forceinline__ int swz64i(int r, int c) { return r * 64 + (c ^ ((r & 7) << 2)); }

// =====================================================================
// pre-pass 1: round X to tf32 grid
// =====================================================================
__global__ void round_x_kernel(const float* __restrict__ in, float* __restrict__ out) {
    int i = blockIdx.x * blockDim.x + threadIdx.x;
    float4 v = ((const float4*)in)[i];
    v.x = rna_tf32(v.x); v.y = rna_tf32(v.y);
    v.z = rna_tf32(v.z); v.w = rna_tf32(v.w);
    ((float4*)out)[i] = v;
}

// =====================================================================
// pre-pass 2: transpose weights [K,N] -> [N,K] with tf32 rounding
// =====================================================================
__global__ void transpose_w_kernel(const float* __restrict__ W0, const float* __restrict__ W1,
                                   const float* __restrict__ W2, const float* __restrict__ W3,
                                   float* __restrict__ out) {
    __shared__ float s[32][33];
    const int z = blockIdx.z;
    const float* W = (z == 0) ? W0 : (z == 1) ? W1 : (z == 2) ? W2 : W3;
    float* O = out + (size_t)z * NK;
    const int bx = blockIdx.x * 32, by = blockIdx.y * 32;
    const int tx = threadIdx.x, ty = threadIdx.y;
#pragma unroll
    for (int i = 0; i < 4; i++)
        s[ty + 8 * i][tx] = W[(size_t)(by + ty + 8 * i) * Dd + bx + tx];
    __syncthreads();
#pragma unroll
    for (int i = 0; i < 4; i++)
        O[(size_t)(bx + ty + 8 * i) * Dd + by + tx] = rna_tf32(s[tx][ty + 8 * i]);
}

// =====================================================================
// pre-pass 3: background K -> g_Kh second half (alpha * tf32)
// =====================================================================
__global__ void bg_fill_k(const float* __restrict__ Kbg) {
    int i = blockIdx.x * blockDim.x + threadIdx.x;     // float4 idx over 80*1024*16
    float4 v = ((const float4*)Kbg)[i];
    v.x = rna_tf32(v.x * ALPHA); v.y = rna_tf32(v.y * ALPHA);
    v.z = rna_tf32(v.z * ALPHA); v.w = rna_tf32(v.w * ALPHA);
    const int bh = i >> 14;            // /(1024*16)
    const int rem = i & 16383;         // j*16 + d4
    ((float4*)g_Kh)[(size_t)bh * 32768 + 16384 + rem] = v;
}

// =====================================================================
// pre-pass 4: background V -> g_Vt second half (transpose + alpha + tf32)
// =====================================================================
__global__ void bg_fill_v(const float* __restrict__ Vbg) {
    __shared__ float s[32][33];
    const int bh = blockIdx.z;
    const int bj = blockIdx.x * 32, bd = blockIdx.y * 32;
    const int tx = threadIdx.x, ty = threadIdx.y;   // 32 x 8
#pragma unroll
    for (int i = 0; i < 4; i++)
        s[ty + 8 * i][tx] = Vbg[((size_t)bh * Ls + bj + ty + 8 * i) * DHc + bd + tx];
    __syncthreads();
#pragma unroll
    for (int i = 0; i < 4; i++)
        g_Vt[((size_t)bh * DHc + bd + ty + 8 * i) * KV + Ls + bj + tx] =
            rna_tf32(s[tx][ty + 8 * i] * ALPHA);
}

// =====================================================================
// tf32 mma.sync GEMM with ldmatrix fragment loads.
// C[M,N] = A[M,K] @ Wt[N,K]^T. 128x128 CTA, 8 warps 2m x 4n, K chunk 32,
// 3-stage cp.async. mode 0: QKV epilogue into g_Qh/g_Kh/g_Vt. mode 1: plain+bias.
// =====================================================================
constexpr int GK_SMEM = 3 * 32768 + 1024;

__device__ __forceinline__ void gk_load_chunk(const float* __restrict__ A,
                                              const float* __restrict__ Wt,
                                              int mblk, int nblk, int kc,
                                              uint32_t aB, uint32_t bB, int t) {
#pragma unroll
    for (int u = 0; u < 4; u++) {
        const int seg = u * 256 + t;
        const int row = seg >> 3, q = seg & 7;
        const uint32_t off = (uint32_t)(row * 128 + ((q * 16) ^ ((row & 7) << 4)));
        cpasync16(aB + off, A + (size_t)(mblk + row) * Dd + kc + q * 4);
        cpasync16(bB + off, Wt + (size_t)(nblk + row) * Dd + kc + q * 4);
    }
    asm volatile("cp.async.commit_group;" ::: "memory");
}

__global__ __launch_bounds__(256)
void gemm_mma_kernel(const float* __restrict__ A,
                     const float* __restrict__ Wt0, const float* __restrict__ Wt1,
                     const float* __restrict__ Wt2,
                     float* __restrict__ C, const float* __restrict__ bias, int mode)
{
    const int z = blockIdx.z;
    const float* __restrict__ Wt = (z == 0) ? Wt0 : (z == 1) ? Wt1 : Wt2;
    const int mblk = blockIdx.y * 128, nblk = blockIdx.x * 128;
    const int t = threadIdx.x, w = t >> 5, lane = t & 31;

    extern __shared__ float dysm[];
    const uint32_t raw = smem_u32(dysm);
    const uint32_t sbu = (raw + 1023u) & ~1023u;

    float acc[4][4][4];
#pragma unroll
    for (int i = 0; i < 4; i++)
#pragma unroll
        for (int j = 0; j < 4; j++)
#pragma unroll
            for (int k = 0; k < 4; k++) acc[i][j][k] = 0.f;

    const int wm = (w & 1) * 64, wn = (w >> 1) * 32;
    const int lq = lane >> 2, lr = lane & 3;
    const int g = lane >> 3, i8 = lane & 7;
    const int xr = i8 << 2;                       // swizzle XOR (float cols)
    const int arow = wm + ((g & 1) << 3) + i8;    // A ldmatrix row
    const int acoff = (g >> 1) * 4;
    const int brow = wn + ((g >> 1) << 3) + i8;   // B ldmatrix row
    const int bcoff = (g & 1) * 4;

    const int nch = Dd / 32;  // 40

#pragma unroll
    for (int c = 0; c < 3; c++)
        gk_load_chunk(A, Wt, mblk, nblk, c * 32, sbu + c * 32768, sbu + c * 32768 + 16384, t);

#pragma unroll 1
    for (int i = 0; i < nch; i++) {
        const int s = i - (i / 3) * 3;
        if (i <= nch - 3)      asm volatile("cp.async.wait_group 2;" ::: "memory");
        else if (i == nch - 2) asm volatile("cp.async.wait_group 1;" ::: "memory");
        else                   asm volatile("cp.async.wait_group 0;" ::: "memory");
        __syncthreads();

        const uint32_t asb = sbu + s * 32768;
        const uint32_t bsb = asb + 16384;
#pragma unroll
        for (int ks = 0; ks < 4; ks++) {
            uint32_t af[4][4];
#pragma unroll
            for (int f = 0; f < 4; f++)
                ldsm4(af[f], asb + 4u * ((arow + 16 * f) * 32 + ((ks * 8 + acoff) ^ xr)));
            uint32_t bf[2][4];
#pragma unroll
            for (int fp = 0; fp < 2; fp++)
                ldsm4(bf[fp], bsb + 4u * ((brow + 16 * fp) * 32 + ((ks * 8 + bcoff) ^ xr)));
#pragma unroll
            for (int f = 0; f < 4; f++) {
                mma8(acc[f][0], af[f], bf[0][0], bf[0][1]);
                mma8(acc[f][1], af[f], bf[0][2], bf[0][3]);
                mma8(acc[f][2], af[f], bf[1][0], bf[1][1]);
                mma8(acc[f][3], af[f], bf[1][2], bf[1][3]);
            }
        }

        if (i + 3 < nch) {
            __syncthreads();
            gk_load_chunk(A, Wt, mblk, nblk, (i + 3) * 32,
                          sbu + s * 32768, sbu + s * 32768 + 16384, t);
        }
    }

    // ---- epilogue ----
#pragma unroll
    for (int f = 0; f < 4; f++) {
#pragma unroll
        for (int fn = 0; fn < 4; fn++) {
            const int r = mblk + wm + 16 * f + lq;
            const int cc = nblk + wn + 8 * fn + 2 * lr;
            float v0 = acc[f][fn][0], v1 = acc[f][fn][1];
            float v2 = acc[f][fn][2], v3 = acc[f][fn][3];
            if (mode == 1) {
                const float b0 = bias ? bias[cc] : 0.f, b1 = bias ? bias[cc + 1] : 0.f;
                *(float2*)&C[(size_t)r * Dd + cc]       = make_float2(v0 + b0, v1 + b1);
                *(float2*)&C[(size_t)(r + 8) * Dd + cc] = make_float2(v2 + b0, v3 + b1);
            } else {
                const int h = cc >> 6, d = cc & 63;
                const int b4 = r >> 10, l = r & 1023;
                const int bh = b4 * Hh + h;
                if (z == 0) {
                    *(float2*)&g_Qh[((size_t)bh * Ls + l) * 64 + d] =
                        make_float2(rna_tf32(v0 * SCALE), rna_tf32(v1 * SCALE));
                    *(float2*)&g_Qh[((size_t)bh * Ls + l + 8) * 64 + d] =
                        make_float2(rna_tf32(v2 * SCALE), rna_tf32(v3 * SCALE));
                } else if (z == 1) {
                    *(float2*)&g_Kh[((size_t)bh * KV + l) * 64 + d] =
                        make_float2(rna_tf32(v0), rna_tf32(v1));
                    *(float2*)&g_Kh[((size_t)bh * KV + l + 8) * 64 + d] =
                        make_float2(rna_tf32(v2), rna_tf32(v3));
                } else {
                    g_Vt[((size_t)bh * 64 + d) * KV + l]         = rna_tf32(v0);
                    g_Vt[((size_t)bh * 64 + d + 1) * KV + l]     = rna_tf32(v1);
                    g_Vt[((size_t)bh * 64 + d) * KV + l + 8]     = rna_tf32(v2);
                    g_Vt[((size_t)bh * 64 + d + 1) * KV + l + 8] = rna_tf32(v3);
                }
            }
        }
    }
}

// =====================================================================
// Flash attention, tf32 mma + ldmatrix + register softmax + cp.async DB.
// CTA = 128 q-rows x one head. smem: Ps/Qs 32KB, Ks[2] 32KB, Vs[2] 32KB.
// =====================================================================
constexpr int ATT_SMEM = 24576 * 4;   // 96 KB

__device__ __forceinline__ void load_kv_tile(int bh, int jt, uint32_t kB, uint32_t vB, int t) {
    const float* ksrc = g_Kh + ((size_t)bh * KV + jt * 64) * 64;
    const float* vsrc = g_Vt + (size_t)bh * 64 * KV + jt * 64;
#pragma unroll
    for (int u = 0; u < 4; u++) {
        const int seg = u * 256 + t;
        const int row = seg >> 4, c4 = seg & 15;
        const uint32_t off = 4u * (row * 64 + ((c4 * 4) ^ ((row & 7) << 2)));
        cpasync16(kB + off, ksrc + row * 64 + c4 * 4);
        cpasync16(vB + off, vsrc + (size_t)row * KV + c4 * 4);
    }
    asm volatile("cp.async.commit_group;" ::: "memory");
}

__global__ __launch_bounds__(256)
void attn_kernel()
{
    extern __shared__ float smf[];
    const uint32_t psB = smem_u32(smf);
    const uint32_t ksB0 = psB + 8192 * 4;
    const uint32_t vsB0 = psB + 16384 * 4;

    const int t = threadIdx.x, w = t >> 5, lane = t & 31;
    const int qblk = blockIdx.x * 128;
    const int bh = blockIdx.y;
    const int b = bh / Hh, h = bh % Hh;
    const int lq = lane >> 2, lr = lane & 3;
    const int g = lane >> 3, i8 = lane & 7;
    const int xr = i8 << 2;
    const int rA = w * 16 + lq;

    // A-type ldmatrix geometry (Ps/Q region, 64-col rows)
    const int prow = w * 16 + ((g & 1) << 3) + i8;
    const int pcoff = (g >> 1) * 4;
    const uint32_t pRowB = psB + 4u * (prow * 64);
    // B-type (Ks/Vs)
    const int brow8 = ((g >> 1) << 3) + i8;
    const int bcoff = (g & 1) * 4;

    // ---- stage Q into Ps region + KV tile 0 ----
    {
        const float* qsrc = g_Qh + ((size_t)bh * Ls + qblk) * 64;
#pragma unroll
        for (int u = 0; u < 8; u++) {
            const int seg = u * 256 + t;
            const int row = seg >> 4, c4 = seg & 15;
            cpasync16(psB + 4u * (row * 64 + ((c4 * 4) ^ ((row & 7) << 2))),
                      qsrc + row * 64 + c4 * 4);
        }
        asm volatile("cp.async.commit_group;" ::: "memory");
    }
    load_kv_tile(bh, 0, ksB0, vsB0, t);
    asm volatile("cp.async.wait_group 0;" ::: "memory");
    __syncthreads();

    // ---- Q fragments, resident for the whole kv loop ----
    uint32_t qf[8][4];
#pragma unroll
    for (int kk = 0; kk < 8; kk++)
        ldsm4(qf[kk], pRowB + 4u * ((kk * 8 + pcoff) ^ xr));

    float m0 = -1e30f, m1 = -1e30f, l0 = 0.f, l1 = 0.f;
    float acc[8][4];
#pragma unroll
    for (int fn = 0; fn < 8; fn++)
#pragma unroll
        for (int j = 0; j < 4; j++) acc[fn][j] = 0.f;

#pragma unroll 1
    for (int jt = 0; jt < 32; jt++) {
        const int s = jt & 1;
        __syncthreads();                                  // PV(jt-1) done; Q frags read
        if (jt + 1 < 32) {
            load_kv_tile(bh, jt + 1, ksB0 + (s ^ 1) * 16384, vsB0 + (s ^ 1) * 16384, t);
            asm volatile("cp.async.wait_group 1;" ::: "memory");
        } else {
            asm volatile("cp.async.wait_group 0;" ::: "memory");
        }
        __syncthreads();                                  // tile jt visible

        const uint32_t kB = ksB0 + s * 16384;
        const uint32_t vB = vsB0 + s * 16384;

        // ---- S = Q K^T ----
        float sacc[8][4];
#pragma unroll
        for (int fn = 0; fn < 8; fn++)
#pragma unroll
            for (int j = 0; j < 4; j++) sacc[fn][j] = 0.f;

#pragma unroll
        for (int kk = 0; kk < 8; kk++) {
            const uint32_t colo = 4u * ((kk * 8 + bcoff) ^ xr);
#pragma unroll
            for (int fp = 0; fp < 4; fp++) {
                uint32_t kf[4];
                ldsm4(kf, kB + 4u * ((brow8 + 16 * fp) * 64) + colo);
                mma8(sacc[2 * fp],     qf[kk], kf[0], kf[1]);
                mma8(sacc[2 * fp + 1], qf[kk], kf[2], kf[3]);
            }
        }

        // ---- register softmax (rows rA, rA+8) ----
        float mx0 = -1e30f, mx1 = -1e30f;
#pragma unroll
        for (int fn = 0; fn < 8; fn++) {
            mx0 = fmaxf(mx0, fmaxf(sacc[fn][0], sacc[fn][1]));
            mx1 = fmaxf(mx1, fmaxf(sacc[fn][2], sacc[fn][3]));
        }
        mx0 = fmaxf(mx0, __shfl_xor_sync(0xffffffffu, mx0, 1));
        mx0 = fmaxf(mx0, __shfl_xor_sync(0xffffffffu, mx0, 2));
        mx1 = fmaxf(mx1, __shfl_xor_sync(0xffffffffu, mx1, 1));
        mx1 = fmaxf(mx1, __shfl_xor_sync(0xffffffffu, mx1, 2));
        const float mn0 = fmaxf(m0, mx0), mn1 = fmaxf(m1, mx1);
        const float cf0 = __expf(m0 - mn0), cf1 = __expf(m1 - mn1);
        float s0 = 0.f, s1 = 0.f;
#pragma unroll
        for (int fn = 0; fn < 8; fn++) {
            const float p0 = __expf(sacc[fn][0] - mn0);
            const float p1 = __expf(sacc[fn][1] - mn0);
            const float p2 = __expf(sacc[fn][2] - mn1);
            const float p3 = __expf(sacc[fn][3] - mn1);
            s0 += p0 + p1; s1 += p2 + p3;
            const int c = fn * 8 + 2 * lr;
            *(float2*)&smf[swz64i(rA, c)]     = make_float2(rna_tf32(p0), rna_tf32(p1));
            *(float2*)&smf[swz64i(rA + 8, c)] = make_float2(rna_tf32(p2), rna_tf32(p3));
        }
        s0 += __shfl_xor_sync(0xffffffffu, s0, 1);
        s0 += __shfl_xor_sync(0xffffffffu, s0, 2);
        s1 += __shfl_xor_sync(0xffffffffu, s1, 1);
        s1 += __shfl_xor_sync(0xffffffffu, s1, 2);
        l0 = l0 * cf0 + s0; l1 = l1 * cf1 + s1;
        m0 = mn0; m1 = mn1;
#pragma unroll
        for (int fn = 0; fn < 8; fn++) {
            acc[fn][0] *= cf0; acc[fn][1] *= cf0;
            acc[fn][2] *= cf1; acc[fn][3] *= cf1;
        }
        __syncthreads();                                  // Ps visible

        // ---- O += P V ----
#pragma unroll
        for (int kk = 0; kk < 8; kk++) {
            uint32_t pf[4];
            ldsm4(pf, pRowB + 4u * ((kk * 8 + pcoff) ^ xr));
            const uint32_t colo = 4u * ((kk * 8 + bcoff) ^ xr);
#pragma unroll
            for (int fp = 0; fp < 4; fp++) {
                uint32_t vf[4];
                ldsm4(vf, vB + 4u * ((brow8 + 16 * fp) * 64) + colo);
                mma8(acc[2 * fp],     pf, vf[0], vf[1]);
                mma8(acc[2 * fp + 1], pf, vf[2], vf[3]);
            }
        }
    }

    // ---- epilogue: /l, tf32 round, scatter to g_CTX ----
    const float inv0 = 1.f / l0, inv1 = 1.f / l1;
    const size_t rowL = (size_t)(b * Ls + qblk + rA) * Dd + h * 64;
#pragma unroll
    for (int fn = 0; fn < 8; fn++) {
        const int c = fn * 8 + 2 * lr;
        *(float2*)&g_CTX[rowL + c] =
            make_float2(rna_tf32(acc[fn][0] * inv0), rna_tf32(acc[fn][1] * inv0));
        *(float2*)&g_CTX[rowL + (size_t)8 * Dd + c] =
            make_float2(rna_tf32(acc[fn][2] * inv1), rna_tf32(acc[fn][3] * inv1));
    }
}

// =====================================================================
// launch
// =====================================================================
extern "C" void kernel_launch(void* const* d_in, const int* in_sizes, int n_in,
                              void* d_out, int out_size)
{
    const float* X   = (const float*)d_in[0];
    const float* Wq  = (const float*)d_in[1];
    const float* Wk  = (const float*)d_in[2];
    const float* Wv  = (const float*)d_in[3];
    const float* Wo  = (const float*)d_in[4];
    const float* bo  = (const float*)d_in[5];
    const float* Kbg = (const float*)d_in[6];
    const float* Vbg = (const float*)d_in[7];
    float* out = (float*)d_out;

    float *CTX, *Wt, *Xt;
    cudaGetSymbolAddress((void**)&CTX, g_CTX);
    cudaGetSymbolAddress((void**)&Wt,  g_Wt);
    cudaGetSymbolAddress((void**)&Xt,  g_Xt);

    // pre-passes
    round_x_kernel<<<Mrows * Dd / (256 * 4), 256>>>(X, Xt);
    transpose_w_kernel<<<dim3(Dd / 32, Dd / 32, 4), dim3(32, 8)>>>(Wq, Wk, Wv, Wo, Wt);
    bg_fill_k<<<BH * Ls * DHc / (4 * 256), 256>>>(Kbg);
    bg_fill_v<<<dim3(Ls / 32, DHc / 32, BH), dim3(32, 8)>>>(Vbg);

    // 1) fused QKV projections -> g_Qh / g_Kh / g_Vt
    cudaFuncSetAttribute(gemm_mma_kernel, cudaFuncAttributeMaxDynamicSharedMemorySize, GK_SMEM);
    dim3 g1(Dd / 128, Mrows / 128, 3);
    gemm_mma_kernel<<<g1, 256, GK_SMEM>>>(Xt, Wt, Wt + NK, Wt + 2 * NK, nullptr, nullptr, 0);

    // 2) attention
    cudaFuncSetAttribute(attn_kernel, cudaFuncAttributeMaxDynamicSharedMemorySize, ATT_SMEM);
    attn_kernel<<<dim3(Ls / 128, BH), 256, ATT_SMEM>>>();

    // 3) output projection (+bias)
    dim3 g3(Dd / 128, Mrows / 128, 1);
    gemm_mma_kernel<<<g3, 256, GK_SMEM>>>(CTX, Wt + 3 * NK, Wt + 3 * NK, Wt + 3 * NK,
                                          out, bo, 1);
}

// round 6
// speedup vs baseline: 3.7671x; 1.0068x over previous
#include <cuda_runtime.h>
#include <cstdint>

// ---------------- problem constants ----------------
constexpr int Bb = 4, Ls = 1024, Dd = 1280, Hh = 20, DHc = 64;
constexpr int Mrows = Bb * Ls;            // 4096
constexpr float ALPHA = 0.48f;
constexpr float SCALE = 0.125f;           // 1/sqrt(64)
constexpr int NK = Dd * Dd;
constexpr int BH = Bb * Hh;               // 80
constexpr int KV = 2 * Ls;                // 2048

// ---------------- device scratch ----------------
__device__ float g_CTX[Mrows * Dd];
__device__ float g_Wt[4 * NK];            // transposed + tf32-rounded weights
__device__ float g_Xt[Mrows * Dd];        // tf32-rounded X
__device__ float g_Qh[BH * Ls * DHc];     // Q*SCALE, tf32, [bh][q][d]
__device__ float g_Kh[BH * KV * DHc];     // K (fg + alpha*bg), tf32, [bh][key][d]
__device__ float g_Vt[BH * DHc * KV];     // V transposed, tf32, [bh][d][key]

// ---------------- helpers ----------------
__device__ __forceinline__ uint32_t smem_u32(const void* p) {
    uint32_t a;
    asm("{ .reg .u64 t; cvta.to.shared.u64 t, %1; cvt.u32.u64 %0, t; }" : "=r"(a) : "l"(p));
    return a;
}
__device__ __forceinline__ float rna_tf32(float x) {
    float r; asm("cvt.rna.tf32.f32 %0, %1;" : "=f"(r) : "f"(x)); return r;
}
__device__ __forceinline__ void mma8(float* d, const uint32_t* a, uint32_t b0, uint32_t b1) {
    asm volatile("mma.sync.aligned.m16n8k8.row.col.f32.tf32.tf32.f32 "
                 "{%0,%1,%2,%3}, {%4,%5,%6,%7}, {%8,%9}, {%0,%1,%2,%3};"
                 : "+f"(d[0]), "+f"(d[1]), "+f"(d[2]), "+f"(d[3])
                 : "r"(a[0]), "r"(a[1]), "r"(a[2]), "r"(a[3]), "r"(b0), "r"(b1));
}
__device__ __forceinline__ void ldsm4(uint32_t* r, uint32_t addr) {
    asm volatile("ldmatrix.sync.aligned.m8n8.x4.shared.b16 {%0,%1,%2,%3}, [%4];"
                 : "=r"(r[0]), "=r"(r[1]), "=r"(r[2]), "=r"(r[3]) : "r"(addr));
}
__device__ __forceinline__ void cpasync16(uint32_t dst, const void* src) {
    asm volatile("cp.async.cg.shared.global [%0], [%1], 16;" :: "r"(dst), "l"(src) : "memory");
}
__device__ __forceinline__ int swz64i(int r, int c) { return r * 64 + (c ^ ((r & 7) << 2)); }

// =====================================================================
// pre-pass 1: round X to tf32 grid
// =====================================================================
__global__ void round_x_kernel(const float* __restrict__ in, float* __restrict__ out) {
    int i = blockIdx.x * blockDim.x + threadIdx.x;
    float4 v = ((const float4*)in)[i];
    v.x = rna_tf32(v.x); v.y = rna_tf32(v.y);
    v.z = rna_tf32(v.z); v.w = rna_tf32(v.w);
    ((float4*)out)[i] = v;
}

// =====================================================================
// pre-pass 2: transpose weights [K,N] -> [N,K] with tf32 rounding
// =====================================================================
__global__ void transpose_w_kernel(const float* __restrict__ W0, const float* __restrict__ W1,
                                   const float* __restrict__ W2, const float* __restrict__ W3,
                                   float* __restrict__ out) {
    __shared__ float s[32][33];
    const int z = blockIdx.z;
    const float* W = (z == 0) ? W0 : (z == 1) ? W1 : (z == 2) ? W2 : W3;
    float* O = out + (size_t)z * NK;
    const int bx = blockIdx.x * 32, by = blockIdx.y * 32;
    const int tx = threadIdx.x, ty = threadIdx.y;
#pragma unroll
    for (int i = 0; i < 4; i++)
        s[ty + 8 * i][tx] = W[(size_t)(by + ty + 8 * i) * Dd + bx + tx];
    __syncthreads();
#pragma unroll
    for (int i = 0; i < 4; i++)
        O[(size_t)(bx + ty + 8 * i) * Dd + by + tx] = rna_tf32(s[tx][ty + 8 * i]);
}

// =====================================================================
// pre-pass 3: background K -> g_Kh second half (alpha * tf32)
// =====================================================================
__global__ void bg_fill_k(const float* __restrict__ Kbg) {
    int i = blockIdx.x * blockDim.x + threadIdx.x;
    float4 v = ((const float4*)Kbg)[i];
    v.x = rna_tf32(v.x * ALPHA); v.y = rna_tf32(v.y * ALPHA);
    v.z = rna_tf32(v.z * ALPHA); v.w = rna_tf32(v.w * ALPHA);
    const int bh = i >> 14;
    const int rem = i & 16383;
    ((float4*)g_Kh)[(size_t)bh * 32768 + 16384 + rem] = v;
}

// =====================================================================
// pre-pass 4: background V -> g_Vt second half (transpose + alpha + tf32)
// =====================================================================
__global__ void bg_fill_v(const float* __restrict__ Vbg) {
    __shared__ float s[32][33];
    const int bh = blockIdx.z;
    const int bj = blockIdx.x * 32, bd = blockIdx.y * 32;
    const int tx = threadIdx.x, ty = threadIdx.y;
#pragma unroll
    for (int i = 0; i < 4; i++)
        s[ty + 8 * i][tx] = Vbg[((size_t)bh * Ls + bj + ty + 8 * i) * DHc + bd + tx];
    __syncthreads();
#pragma unroll
    for (int i = 0; i < 4; i++)
        g_Vt[((size_t)bh * DHc + bd + ty + 8 * i) * KV + Ls + bj + tx] =
            rna_tf32(s[tx][ty + 8 * i] * ALPHA);
}

// =====================================================================
// tf32 mma.sync GEMM with ldmatrix. 128x128 CTA, 8 warps 2m x 4n,
// K chunk 32, 3-stage cp.async. 2 CTAs/SM via launch_bounds + carveout.
// mode 0: QKV epilogue into g_Qh/g_Kh/g_Vt. mode 1: plain + bias.
// =====================================================================
constexpr int GK_SMEM = 3 * 32768 + 1024;

__device__ __forceinline__ void gk_load_chunk(const float* __restrict__ A,
                                              const float* __restrict__ Wt,
                                              int mblk, int nblk, int kc,
                                              uint32_t aB, uint32_t bB, int t) {
#pragma unroll
    for (int u = 0; u < 4; u++) {
        const int seg = u * 256 + t;
        const int row = seg >> 3, q = seg & 7;
        const uint32_t off = (uint32_t)(row * 128 + ((q * 16) ^ ((row & 7) << 4)));
        cpasync16(aB + off, A + (size_t)(mblk + row) * Dd + kc + q * 4);
        cpasync16(bB + off, Wt + (size_t)(nblk + row) * Dd + kc + q * 4);
    }
    asm volatile("cp.async.commit_group;" ::: "memory");
}

__global__ __launch_bounds__(256, 2)
void gemm_mma_kernel(const float* __restrict__ A,
                     const float* __restrict__ Wt0, const float* __restrict__ Wt1,
                     const float* __restrict__ Wt2,
                     float* __restrict__ C, const float* __restrict__ bias, int mode)
{
    const int z = blockIdx.z;
    const float* __restrict__ Wt = (z == 0) ? Wt0 : (z == 1) ? Wt1 : Wt2;
    const int mblk = blockIdx.y * 128, nblk = blockIdx.x * 128;
    const int t = threadIdx.x, w = t >> 5, lane = t & 31;

    extern __shared__ float dysm[];
    const uint32_t raw = smem_u32(dysm);
    const uint32_t sbu = (raw + 1023u) & ~1023u;

    float acc[4][4][4];
#pragma unroll
    for (int i = 0; i < 4; i++)
#pragma unroll
        for (int j = 0; j < 4; j++)
#pragma unroll
            for (int k = 0; k < 4; k++) acc[i][j][k] = 0.f;

    const int wm = (w & 1) * 64, wn = (w >> 1) * 32;
    const int lq = lane >> 2, lr = lane & 3;
    const int g = lane >> 3, i8 = lane & 7;
    const int xr = i8 << 2;
    const int arow = wm + ((g & 1) << 3) + i8;
    const int acoff = (g >> 1) * 4;
    const int brow = wn + ((g >> 1) << 3) + i8;
    const int bcoff = (g & 1) * 4;

    const int nch = Dd / 32;  // 40

#pragma unroll
    for (int c = 0; c < 3; c++)
        gk_load_chunk(A, Wt, mblk, nblk, c * 32, sbu + c * 32768, sbu + c * 32768 + 16384, t);

#pragma unroll 1
    for (int i = 0; i < nch; i++) {
        const int s = i - (i / 3) * 3;
        if (i <= nch - 3)      asm volatile("cp.async.wait_group 2;" ::: "memory");
        else if (i == nch - 2) asm volatile("cp.async.wait_group 1;" ::: "memory");
        else                   asm volatile("cp.async.wait_group 0;" ::: "memory");
        __syncthreads();

        const uint32_t asb = sbu + s * 32768;
        const uint32_t bsb = asb + 16384;
#pragma unroll
        for (int ks = 0; ks < 4; ks++) {
            uint32_t af[4][4];
#pragma unroll
            for (int f = 0; f < 4; f++)
                ldsm4(af[f], asb + 4u * ((arow + 16 * f) * 32 + ((ks * 8 + acoff) ^ xr)));
            uint32_t bf[2][4];
#pragma unroll
            for (int fp = 0; fp < 2; fp++)
                ldsm4(bf[fp], bsb + 4u * ((brow + 16 * fp) * 32 + ((ks * 8 + bcoff) ^ xr)));
#pragma unroll
            for (int f = 0; f < 4; f++) {
                mma8(acc[f][0], af[f], bf[0][0], bf[0][1]);
                mma8(acc[f][1], af[f], bf[0][2], bf[0][3]);
                mma8(acc[f][2], af[f], bf[1][0], bf[1][1]);
                mma8(acc[f][3], af[f], bf[1][2], bf[1][3]);
            }
        }

        if (i + 3 < nch) {
            __syncthreads();
            gk_load_chunk(A, Wt, mblk, nblk, (i + 3) * 32,
                          sbu + s * 32768, sbu + s * 32768 + 16384, t);
        }
    }

    // ---- epilogue ----
#pragma unroll
    for (int f = 0; f < 4; f++) {
#pragma unroll
        for (int fn = 0; fn < 4; fn++) {
            const int r = mblk + wm + 16 * f + lq;
            const int cc = nblk + wn + 8 * fn + 2 * lr;
            float v0 = acc[f][fn][0], v1 = acc[f][fn][1];
            float v2 = acc[f][fn][2], v3 = acc[f][fn][3];
            if (mode == 1) {
                const float b0 = bias ? bias[cc] : 0.f, b1 = bias ? bias[cc + 1] : 0.f;
                *(float2*)&C[(size_t)r * Dd + cc]       = make_float2(v0 + b0, v1 + b1);
                *(float2*)&C[(size_t)(r + 8) * Dd + cc] = make_float2(v2 + b0, v3 + b1);
            } else {
                const int h = cc >> 6, d = cc & 63;
                const int b4 = r >> 10, l = r & 1023;
                const int bh = b4 * Hh + h;
                if (z == 0) {
                    *(float2*)&g_Qh[((size_t)bh * Ls + l) * 64 + d] =
                        make_float2(rna_tf32(v0 * SCALE), rna_tf32(v1 * SCALE));
                    *(float2*)&g_Qh[((size_t)bh * Ls + l + 8) * 64 + d] =
                        make_float2(rna_tf32(v2 * SCALE), rna_tf32(v3 * SCALE));
                } else if (z == 1) {
                    *(float2*)&g_Kh[((size_t)bh * KV + l) * 64 + d] =
                        make_float2(rna_tf32(v0), rna_tf32(v1));
                    *(float2*)&g_Kh[((size_t)bh * KV + l + 8) * 64 + d] =
                        make_float2(rna_tf32(v2), rna_tf32(v3));
                } else {
                    g_Vt[((size_t)bh * 64 + d) * KV + l]         = rna_tf32(v0);
                    g_Vt[((size_t)bh * 64 + d + 1) * KV + l]     = rna_tf32(v1);
                    g_Vt[((size_t)bh * 64 + d) * KV + l + 8]     = rna_tf32(v2);
                    g_Vt[((size_t)bh * 64 + d + 1) * KV + l + 8] = rna_tf32(v3);
                }
            }
        }
    }
}

// =====================================================================
// Flash attention v2: CTA = 256 q-rows x one head, 8 warps (32 q-rows/warp).
// K fragments shared across the warp's two 16-row blocks (S phase),
// V fragments shared across both blocks (PV phase).
// smem: Qs 64KB | Ps 64KB | K db 32KB | V db 32KB = 192KB. 1 CTA/SM.
// =====================================================================
constexpr int ATT_SMEM = 49152 * 4;   // 192 KB

__device__ __forceinline__ void load_kv_tile(int bh, int jt, uint32_t kB, uint32_t vB, int t) {
    const float* ksrc = g_Kh + ((size_t)bh * KV + jt * 64) * 64;
    const float* vsrc = g_Vt + (size_t)bh * 64 * KV + jt * 64;
#pragma unroll
    for (int u = 0; u < 4; u++) {
        const int seg = u * 256 + t;
        const int row = seg >> 4, c4 = seg & 15;
        const uint32_t off = 4u * (row * 64 + ((c4 * 4) ^ ((row & 7) << 2)));
        cpasync16(kB + off, ksrc + row * 64 + c4 * 4);
        cpasync16(vB + off, vsrc + (size_t)row * KV + c4 * 4);
    }
    asm volatile("cp.async.commit_group;" ::: "memory");
}

// softmax for one 16-row block; stores rna-rounded P into Ps (warp-private rows)
__device__ __forceinline__ void softmax_block(float sacc[8][4], float& m0, float& m1,
                                              float& l0, float& l1, float acc[8][4],
                                              float* Ps, int rowLoc, int lr) {
    float mx0 = -1e30f, mx1 = -1e30f;
#pragma unroll
    for (int fn = 0; fn < 8; fn++) {
        mx0 = fmaxf(mx0, fmaxf(sacc[fn][0], sacc[fn][1]));
        mx1 = fmaxf(mx1, fmaxf(sacc[fn][2], sacc[fn][3]));
    }
    mx0 = fmaxf(mx0, __shfl_xor_sync(0xffffffffu, mx0, 1));
    mx0 = fmaxf(mx0, __shfl_xor_sync(0xffffffffu, mx0, 2));
    mx1 = fmaxf(mx1, __shfl_xor_sync(0xffffffffu, mx1, 1));
    mx1 = fmaxf(mx1, __shfl_xor_sync(0xffffffffu, mx1, 2));
    const float mn0 = fmaxf(m0, mx0), mn1 = fmaxf(m1, mx1);
    const float cf0 = __expf(m0 - mn0), cf1 = __expf(m1 - mn1);
    float s0 = 0.f, s1 = 0.f;
#pragma unroll
    for (int fn = 0; fn < 8; fn++) {
        const float p0 = __expf(sacc[fn][0] - mn0);
        const float p1 = __expf(sacc[fn][1] - mn0);
        const float p2 = __expf(sacc[fn][2] - mn1);
        const float p3 = __expf(sacc[fn][3] - mn1);
        s0 += p0 + p1; s1 += p2 + p3;
        const int c = fn * 8 + 2 * lr;
        *(float2*)&Ps[swz64i(rowLoc, c)]     = make_float2(rna_tf32(p0), rna_tf32(p1));
        *(float2*)&Ps[swz64i(rowLoc + 8, c)] = make_float2(rna_tf32(p2), rna_tf32(p3));
    }
    s0 += __shfl_xor_sync(0xffffffffu, s0, 1);
    s0 += __shfl_xor_sync(0xffffffffu, s0, 2);
    s1 += __shfl_xor_sync(0xffffffffu, s1, 1);
    s1 += __shfl_xor_sync(0xffffffffu, s1, 2);
    l0 = l0 * cf0 + s0; l1 = l1 * cf1 + s1;
    m0 = mn0; m1 = mn1;
#pragma unroll
    for (int fn = 0; fn < 8; fn++) {
        acc[fn][0] *= cf0; acc[fn][1] *= cf0;
        acc[fn][2] *= cf1; acc[fn][3] *= cf1;
    }
}

__global__ __launch_bounds__(256)
void attn_kernel()
{
    extern __shared__ float smf[];
    const uint32_t QsB = smem_u32(smf);
    float* Ps = smf + 16384;
    const uint32_t PsB = QsB + 16384 * 4;
    const uint32_t kB0 = QsB + 32768 * 4;
    const uint32_t vB0 = QsB + 40960 * 4;

    const int t = threadIdx.x, w = t >> 5, lane = t & 31;
    const int qblk = blockIdx.x * 256;
    const int bh = blockIdx.y;
    const int b = bh / Hh, h = bh % Hh;
    const int lq = lane >> 2, lr = lane & 3;
    const int g = lane >> 3, i8 = lane & 7;
    const int xr = i8 << 2;

    // ldmatrix geometry
    const int aRow0 = w * 32 + ((g & 1) << 3) + i8;    // block0 A rows
    const int aRow1 = aRow0 + 16;                      // block1
    const int acoff = (g >> 1) * 4;
    const int brow8 = ((g >> 1) << 3) + i8;
    const int bcoff = (g & 1) * 4;

    // ---- stage Q (256x64) + KV tile 0 ----
    {
        const float* qsrc = g_Qh + ((size_t)bh * Ls + qblk) * 64;
#pragma unroll
        for (int u = 0; u < 16; u++) {
            const int seg = u * 256 + t;
            const int row = seg >> 4, c4 = seg & 15;
            cpasync16(QsB + 4u * (row * 64 + ((c4 * 4) ^ ((row & 7) << 2))),
                      qsrc + row * 64 + c4 * 4);
        }
        asm volatile("cp.async.commit_group;" ::: "memory");
    }
    load_kv_tile(bh, 0, kB0, vB0, t);
    asm volatile("cp.async.wait_group 0;" ::: "memory");
    __syncthreads();

    float m[2][2] = {{-1e30f, -1e30f}, {-1e30f, -1e30f}};
    float l[2][2] = {{0.f, 0.f}, {0.f, 0.f}};
    float acc[2][8][4];
#pragma unroll
    for (int bb = 0; bb < 2; bb++)
#pragma unroll
        for (int fn = 0; fn < 8; fn++)
#pragma unroll
            for (int j = 0; j < 4; j++) acc[bb][fn][j] = 0.f;

#pragma unroll 1
    for (int jt = 0; jt < 32; jt++) {
        const int s = jt & 1;
        __syncthreads();                                  // buffers s^1 free
        if (jt + 1 < 32) {
            load_kv_tile(bh, jt + 1, kB0 + (s ^ 1) * 16384, vB0 + (s ^ 1) * 16384, t);
            asm volatile("cp.async.wait_group 1;" ::: "memory");
        } else {
            asm volatile("cp.async.wait_group 0;" ::: "memory");
        }
        __syncthreads();                                  // tile jt visible

        const uint32_t kB = kB0 + s * 16384;
        const uint32_t vB = vB0 + s * 16384;

        // ---- S phase, both row-blocks sharing K fragments ----
        float s0[8][4], s1[8][4];
#pragma unroll
        for (int fn = 0; fn < 8; fn++)
#pragma unroll
            for (int j = 0; j < 4; j++) { s0[fn][j] = 0.f; s1[fn][j] = 0.f; }

#pragma unroll
        for (int kk = 0; kk < 8; kk++) {
            uint32_t qa0[4], qa1[4];
            const uint32_t acol = 4u * ((kk * 8 + acoff) ^ xr);
            ldsm4(qa0, QsB + 4u * (aRow0 * 64) + acol);
            ldsm4(qa1, QsB + 4u * (aRow1 * 64) + acol);
            const uint32_t colo = 4u * ((kk * 8 + bcoff) ^ xr);
#pragma unroll
            for (int fp = 0; fp < 4; fp++) {
                uint32_t kf[4];
                ldsm4(kf, kB + 4u * ((brow8 + 16 * fp) * 64) + colo);
                mma8(s0[2 * fp],     qa0, kf[0], kf[1]);
                mma8(s0[2 * fp + 1], qa0, kf[2], kf[3]);
                mma8(s1[2 * fp],     qa1, kf[0], kf[1]);
                mma8(s1[2 * fp + 1], qa1, kf[2], kf[3]);
            }
        }

        // ---- softmax both blocks (P is warp-private -> syncwarp only) ----
        softmax_block(s0, m[0][0], m[0][1], l[0][0], l[0][1], acc[0], Ps, w * 32 + lq, lr);
        softmax_block(s1, m[1][0], m[1][1], l[1][0], l[1][1], acc[1], Ps, w * 32 + 16 + lq, lr);
        __syncwarp();

        // ---- PV phase, both row-blocks sharing V fragments ----
#pragma unroll
        for (int kk = 0; kk < 8; kk++) {
            uint32_t pf0[4], pf1[4];
            const uint32_t acol = 4u * ((kk * 8 + acoff) ^ xr);
            ldsm4(pf0, PsB + 4u * (aRow0 * 64) + acol);
            ldsm4(pf1, PsB + 4u * (aRow1 * 64) + acol);
            const uint32_t colo = 4u * ((kk * 8 + bcoff) ^ xr);
#pragma unroll
            for (int fp = 0; fp < 4; fp++) {
                uint32_t vf[4];
                ldsm4(vf, vB + 4u * ((brow8 + 16 * fp) * 64) + colo);
                mma8(acc[0][2 * fp],     pf0, vf[0], vf[1]);
                mma8(acc[0][2 * fp + 1], pf0, vf[2], vf[3]);
                mma8(acc[1][2 * fp],     pf1, vf[0], vf[1]);
                mma8(acc[1][2 * fp + 1], pf1, vf[2], vf[3]);
            }
        }
    }

    // ---- epilogue ----
#pragma unroll
    for (int bb = 0; bb < 2; bb++) {
        const float inv0 = 1.f / l[bb][0], inv1 = 1.f / l[bb][1];
        const int gq = qblk + w * 32 + bb * 16 + lq;
        const size_t rowL = (size_t)(b * Ls + gq) * Dd + h * 64;
#pragma unroll
        for (int fn = 0; fn < 8; fn++) {
            const int c = fn * 8 + 2 * lr;
            *(float2*)&g_CTX[rowL + c] =
                make_float2(rna_tf32(acc[bb][fn][0] * inv0), rna_tf32(acc[bb][fn][1] * inv0));
            *(float2*)&g_CTX[rowL + (size_t)8 * Dd + c] =
                make_float2(rna_tf32(acc[bb][fn][2] * inv1), rna_tf32(acc[bb][fn][3] * inv1));
        }
    }
}

// =====================================================================
// launch
// =====================================================================
extern "C" void kernel_launch(void* const* d_in, const int* in_sizes, int n_in,
                              void* d_out, int out_size)
{
    const float* X   = (const float*)d_in[0];
    const float* Wq  = (const float*)d_in[1];
    const float* Wk  = (const float*)d_in[2];
    const float* Wv  = (const float*)d_in[3];
    const float* Wo  = (const float*)d_in[4];
    const float* bo  = (const float*)d_in[5];
    const float* Kbg = (const float*)d_in[6];
    const float* Vbg = (const float*)d_in[7];
    float* out = (float*)d_out;

    float *CTX, *Wt, *Xt;
    cudaGetSymbolAddress((void**)&CTX, g_CTX);
    cudaGetSymbolAddress((void**)&Wt,  g_Wt);
    cudaGetSymbolAddress((void**)&Xt,  g_Xt);

    // pre-passes
    round_x_kernel<<<Mrows * Dd / (256 * 4), 256>>>(X, Xt);
    transpose_w_kernel<<<dim3(Dd / 32, Dd / 32, 4), dim3(32, 8)>>>(Wq, Wk, Wv, Wo, Wt);
    bg_fill_k<<<BH * Ls * DHc / (4 * 256), 256>>>(Kbg);
    bg_fill_v<<<dim3(Ls / 32, DHc / 32, BH), dim3(32, 8)>>>(Vbg);

    // 1) fused QKV projections -> g_Qh / g_Kh / g_Vt
    cudaFuncSetAttribute(gemm_mma_kernel, cudaFuncAttributeMaxDynamicSharedMemorySize, GK_SMEM);
    cudaFuncSetAttribute(gemm_mma_kernel, cudaFuncAttributePreferredSharedMemoryCarveout, 100);
    dim3 g1(Dd / 128, Mrows / 128, 3);
    gemm_mma_kernel<<<g1, 256, GK_SMEM>>>(Xt, Wt, Wt + NK, Wt + 2 * NK, nullptr, nullptr, 0);

    // 2) attention (q-tile 256)
    cudaFuncSetAttribute(attn_kernel, cudaFuncAttributeMaxDynamicSharedMemorySize, ATT_SMEM);
    cudaFuncSetAttribute(attn_kernel, cudaFuncAttributePreferredSharedMemoryCarveout, 100);
    attn_kernel<<<dim3(Ls / 256, BH), 256, ATT_SMEM>>>();

    // 3) output projection (+bias)
    dim3 g3(Dd / 128, Mrows / 128, 1);
    gemm_mma_kernel<<<g3, 256, GK_SMEM>>>(CTX, Wt + 3 * NK, Wt + 3 * NK, Wt + 3 * NK,
                                          out, bo, 1);
}